// round 10
// baseline (speedup 1.0000x reference)
#include <cuda_runtime.h>
#include <cstdint>

// ModelVoxel: out[p] = f[i,j,k] with i,j,k = (int)clip((x[p]+1)/h, 0, 255),
// h = 2/255, f is 256^3 fp32 (64 MB, mostly L2-resident via evict_last hint).
//
// R9: 8 points per thread (6 front-batched LDG.128 + 8 independent gathers +
// 2 STG.128) to double per-warp MLP and close the latency/overlap gap seen
// at R7 (all pipes 57-69%, none saturated).
//  - x   -> __ldcs (evict-first streaming)
//  - out -> __stcs
//  - f   -> ld.global.nc.L2::cache_hint + createpolicy evict_last

static __device__ __forceinline__ int vox1(float v) {
    const float h = 2.0f / 255.0f;           // replicate reference's fp32 h
    float p = (v + 1.0f) / h;                // same op order as reference
    p = fminf(fmaxf(p, 0.0f), 255.0f);       // clip
    return (int)p;                           // truncation == astype(int32) (p >= 0)
}

static __device__ __forceinline__ uint64_t make_evict_last_policy() {
    uint64_t pol;
    asm("createpolicy.fractional.L2::evict_last.b64 %0, 1.0;" : "=l"(pol));
    return pol;
}

static __device__ __forceinline__ float ldg_pin_l2(const float* p, uint64_t pol) {
    float v;
    asm("ld.global.nc.L2::cache_hint.f32 %0, [%1], %2;"
        : "=f"(v) : "l"(p), "l"(pol));
    return v;
}

__global__ void __launch_bounds__(256) voxel_gather8_kernel(
    const float4* __restrict__ x4,   // 6 float4s per 8 points
    const float*  __restrict__ f,    // 256^3 grid
    float4*       __restrict__ out4, // 2 float4s per 8 points
    int n8)                          // number of 8-point groups
{
    int t = blockIdx.x * blockDim.x + threadIdx.x;
    if (t >= n8) return;

    const uint64_t pol = make_evict_last_policy();

    const float4* p = x4 + 6 * (size_t)t;
    // Front-batch all 6 wide loads -> 6 outstanding LDG.128 per thread.
    float4 a = __ldcs(p + 0);
    float4 b = __ldcs(p + 1);
    float4 c = __ldcs(p + 2);
    float4 d = __ldcs(p + 3);
    float4 e = __ldcs(p + 4);
    float4 g = __ldcs(p + 5);

    // 24 floats = 8 points:
    // p0:(a.x,a.y,a.z) p1:(a.w,b.x,b.y) p2:(b.z,b.w,c.x) p3:(c.y,c.z,c.w)
    // p4:(d.x,d.y,d.z) p5:(d.w,e.x,e.y) p6:(e.z,e.w,g.x) p7:(g.y,g.z,g.w)
    int i0 = (vox1(a.x) << 16) | (vox1(a.y) << 8) | vox1(a.z);
    int i1 = (vox1(a.w) << 16) | (vox1(b.x) << 8) | vox1(b.y);
    int i2 = (vox1(b.z) << 16) | (vox1(b.w) << 8) | vox1(c.x);
    int i3 = (vox1(c.y) << 16) | (vox1(c.z) << 8) | vox1(c.w);
    int i4 = (vox1(d.x) << 16) | (vox1(d.y) << 8) | vox1(d.z);
    int i5 = (vox1(d.w) << 16) | (vox1(e.x) << 8) | vox1(e.y);
    int i6 = (vox1(e.z) << 16) | (vox1(e.w) << 8) | vox1(g.x);
    int i7 = (vox1(g.y) << 16) | (vox1(g.z) << 8) | vox1(g.w);

    // 8 independent gathers in flight.
    float4 o0, o1;
    o0.x = ldg_pin_l2(f + i0, pol);
    o0.y = ldg_pin_l2(f + i1, pol);
    o0.z = ldg_pin_l2(f + i2, pol);
    o0.w = ldg_pin_l2(f + i3, pol);
    o1.x = ldg_pin_l2(f + i4, pol);
    o1.y = ldg_pin_l2(f + i5, pol);
    o1.z = ldg_pin_l2(f + i6, pol);
    o1.w = ldg_pin_l2(f + i7, pol);

    __stcs(out4 + 2 * (size_t)t + 0, o0);
    __stcs(out4 + 2 * (size_t)t + 1, o1);
}

// Tail handler for n not divisible by 8 (not needed for 16777216, but cheap).
__global__ void voxel_gather_tail_kernel(
    const float* __restrict__ x,
    const float* __restrict__ f,
    float*       __restrict__ out,
    int start, int n)
{
    int i = start + blockIdx.x * blockDim.x + threadIdx.x;
    if (i >= n) return;
    const uint64_t pol = make_evict_last_policy();
    int ix = vox1(x[3 * (size_t)i + 0]);
    int iy = vox1(x[3 * (size_t)i + 1]);
    int iz = vox1(x[3 * (size_t)i + 2]);
    out[i] = ldg_pin_l2(f + ((ix << 16) | (iy << 8) | iz), pol);
}

extern "C" void kernel_launch(void* const* d_in, const int* in_sizes, int n_in,
                              void* d_out, int out_size) {
    const float* x = (const float*)d_in[0];   // (N, 3) fp32
    const float* f = (const float*)d_in[1];   // (256,256,256) fp32
    float* out = (float*)d_out;               // (N,) fp32

    int n  = in_sizes[0] / 3;                 // number of points
    int n8 = n / 8;

    if (n8 > 0) {
        int threads = 256;
        int blocks = (n8 + threads - 1) / threads;
        voxel_gather8_kernel<<<blocks, threads>>>(
            (const float4*)x, f, (float4*)out, n8);
    }
    int rem_start = n8 * 8;
    if (rem_start < n) {
        int rem = n - rem_start;
        voxel_gather_tail_kernel<<<(rem + 255) / 256, 256>>>(
            x, f, out, rem_start, n);
    }
}